// round 1
// baseline (speedup 1.0000x reference)
#include <cuda_runtime.h>
#include <cstdint>

// ---------------------------------------------------------------------------
// IoU loss (2D + scatter-rebuilt 3D), HBM-bound. Scratch: 64MB device global.
// ---------------------------------------------------------------------------

#define DMAX 256
#define VOLN (DMAX * DMAX * DMAX)

__device__ float  g_vol[VOLN];
__device__ double g_acc[4];   // [0]=Sum(o2*m2) [1]=Sum(o2+m2) [2]=Sum(vol*m3) [3]=Sum(vol+m3)

// ---------------------------------------------------------------------------
__global__ void zero_kernel() {
    const int tid    = blockIdx.x * blockDim.x + threadIdx.x;
    const int stride = gridDim.x * blockDim.x;
    float4* v4 = reinterpret_cast<float4*>(g_vol);
    const int n4 = VOLN / 4;
    const float4 z = make_float4(0.f, 0.f, 0.f, 0.f);
    for (int i = tid; i < n4; i += stride) v4[i] = z;
    if (blockIdx.x == 0 && threadIdx.x < 4) g_acc[threadIdx.x] = 0.0;
}

// ---------------------------------------------------------------------------
__device__ __forceinline__ void block_reduce_pair(float a, float b,
                                                  double* accA, double* accB) {
    #pragma unroll
    for (int o = 16; o > 0; o >>= 1) {
        a += __shfl_xor_sync(0xFFFFFFFFu, a, o);
        b += __shfl_xor_sync(0xFFFFFFFFu, b, o);
    }
    __shared__ float sa[32], sb[32];
    const int lane = threadIdx.x & 31;
    const int wrp  = threadIdx.x >> 5;
    if (lane == 0) { sa[wrp] = a; sb[wrp] = b; }
    __syncthreads();
    if (wrp == 0) {
        const int nw = (blockDim.x + 31) >> 5;
        a = (lane < nw) ? sa[lane] : 0.f;
        b = (lane < nw) ? sb[lane] : 0.f;
        #pragma unroll
        for (int o = 16; o > 0; o >>= 1) {
            a += __shfl_xor_sync(0xFFFFFFFFu, a, o);
            b += __shfl_xor_sync(0xFFFFFFFFu, b, o);
        }
        if (lane == 0) {
            atomicAdd(accA, (double)a);
            atomicAdd(accB, (double)b);
        }
    }
}

// ---------------------------------------------------------------------------
// Scatter samples into g_vol (racing plain stores == ".set with some winner")
// fused with the 2D IoU partial sums.
__global__ void scatter_and_2d_kernel(const float* __restrict__ o2d,
                                      const float* __restrict__ m2d,
                                      const int*   __restrict__ index,
                                      const int*   __restrict__ midxyz,
                                      int N, int M, int D) {
    const int tid    = blockIdx.x * blockDim.x + threadIdx.x;
    const int stride = gridDim.x * blockDim.x;

    // scatter
    for (int i = tid; i < N; i += stride) {
        const int   id = __ldg(index + i);
        const float v  = __ldg(o2d + id);
        const int x = __ldg(midxyz + 3 * i + 0);
        const int y = __ldg(midxyz + 3 * i + 1);
        const int z = __ldg(midxyz + 3 * i + 2);
        g_vol[((unsigned)x * (unsigned)D + (unsigned)y) * (unsigned)D + (unsigned)z] = v;
    }

    // 2D reduction (vectorized)
    float a = 0.f, b = 0.f;
    const int m4 = M >> 2;
    const float4* o4 = reinterpret_cast<const float4*>(o2d);
    const float4* q4 = reinterpret_cast<const float4*>(m2d);
    for (int i = tid; i < m4; i += stride) {
        const float4 o = o4[i];
        const float4 m = q4[i];
        a += o.x * m.x + o.y * m.y + o.z * m.z + o.w * m.w;
        b += (o.x + m.x) + (o.y + m.y) + (o.z + m.z) + (o.w + m.w);
    }
    // tail (M not multiple of 4)
    for (int i = (m4 << 2) + tid; i < M; i += stride) {
        const float o = o2d[i], m = m2d[i];
        a += o * m;
        b += o + m;
    }
    block_reduce_pair(a, b, &g_acc[0], &g_acc[1]);
}

// ---------------------------------------------------------------------------
__global__ void reduce3d_kernel(const float* __restrict__ mask3d, int n) {
    const int tid    = blockIdx.x * blockDim.x + threadIdx.x;
    const int stride = gridDim.x * blockDim.x;
    float a = 0.f, b = 0.f;
    const int n4 = n >> 2;
    const float4* m4 = reinterpret_cast<const float4*>(mask3d);
    const float4* v4 = reinterpret_cast<const float4*>(g_vol);
    for (int i = tid; i < n4; i += stride) {
        const float4 m = m4[i];
        const float4 v = v4[i];
        a += v.x * m.x + v.y * m.y + v.z * m.z + v.w * m.w;
        b += (v.x + m.x) + (v.y + m.y) + (v.z + m.z) + (v.w + m.w);
    }
    block_reduce_pair(a, b, &g_acc[2], &g_acc[3]);
}

// ---------------------------------------------------------------------------
__global__ void finalize_kernel(float* __restrict__ out) {
    const double eps = 1e-8;
    const double A1 = g_acc[0], B1 = g_acc[1];
    const double A2 = g_acc[2], B2 = g_acc[3];
    const double iou1 = (A1 + eps) / ((B1 - A1) + eps);
    const double iou2 = (A2 + eps) / ((B2 - A2) + eps);
    const double l1 = 1.0 - iou1;
    const double l2 = 1.0 - iou2;
    out[0] = (float)l1;
    out[1] = (float)l2;
    out[2] = (float)(l1 + l2);
}

// ---------------------------------------------------------------------------
extern "C" void kernel_launch(void* const* d_in, const int* in_sizes, int n_in,
                              void* d_out, int out_size) {
    const float* o2d    = (const float*)d_in[0];
    const float* m2d    = (const float*)d_in[1];
    const float* m3d    = (const float*)d_in[2];
    const int*   index  = (const int*)  d_in[3];
    const int*   midxyz = (const int*)  d_in[4];

    const int M  = in_sizes[0];       // H2*W2 elements
    const int V  = in_sizes[2];       // D^3 elements
    const int N  = in_sizes[3];       // scattered samples

    // integer cube root for D
    int D = 1;
    while ((long long)(D + 1) * (D + 1) * (D + 1) <= (long long)V) ++D;
    if (D > DMAX) D = DMAX;           // scratch capacity guard (problem uses 256)

    float* out = (float*)d_out;

    const int TPB = 256;
    const int GRID_ZERO = 148 * 8;
    const int GRID_MAIN = 148 * 16;

    zero_kernel<<<GRID_ZERO, TPB>>>();
    scatter_and_2d_kernel<<<GRID_MAIN, TPB>>>(o2d, m2d, index, midxyz, N, M, D);
    reduce3d_kernel<<<GRID_MAIN, TPB>>>(m3d, V);
    finalize_kernel<<<1, 1>>>(out);
}

// round 2
// speedup vs baseline: 1.0221x; 1.0221x over previous
#include <cuda_runtime.h>
#include <cstdint>

// ---------------------------------------------------------------------------
// IoU loss (2D + scatter-rebuilt 3D) WITHOUT materializing the 3D volume.
//   vol is zero except at scattered voxels, so:
//     inter2 = sum over DISTINCT voxels of winner * m3[voxel]
//     union2 = sum(winner) + sum(m3) - inter2
//   Dedup ("set" semantics = one winner per voxel) via a 2MB bitmap + atomicOr:
//   first thread to set the bit is the winner (winner identity is irrelevant
//   at 1e-3 tolerance; measured ~5e-6).
// ---------------------------------------------------------------------------

#define DMAX   256
#define BITN   ((DMAX * DMAX * DMAX) / 32)   // 512K words = 2MB

__device__ unsigned g_bitmap[BITN];
__device__ double   g_acc[5];
// [0]=S(o2*m2) [1]=S(o2+m2) [2]=S(win*m3) [3]=S(win) [4]=S(m3)

// ---------------------------------------------------------------------------
__global__ void zero_kernel() {
    const int tid    = blockIdx.x * blockDim.x + threadIdx.x;
    const int stride = gridDim.x * blockDim.x;
    uint4* b4 = reinterpret_cast<uint4*>(g_bitmap);
    const uint4 z = make_uint4(0u, 0u, 0u, 0u);
    for (int i = tid; i < BITN / 4; i += stride) b4[i] = z;
    if (blockIdx.x == 0 && threadIdx.x < 5) g_acc[threadIdx.x] = 0.0;
}

// ---------------------------------------------------------------------------
__device__ __forceinline__ void block_reduce_pair(float a, float b,
                                                  double* accA, double* accB) {
    #pragma unroll
    for (int o = 16; o > 0; o >>= 1) {
        a += __shfl_xor_sync(0xFFFFFFFFu, a, o);
        b += __shfl_xor_sync(0xFFFFFFFFu, b, o);
    }
    __shared__ float sa[32], sb[32];
    const int lane = threadIdx.x & 31;
    const int wrp  = threadIdx.x >> 5;
    __syncthreads();                       // safe reuse across calls
    if (lane == 0) { sa[wrp] = a; sb[wrp] = b; }
    __syncthreads();
    if (wrp == 0) {
        const int nw = (blockDim.x + 31) >> 5;
        a = (lane < nw) ? sa[lane] : 0.f;
        b = (lane < nw) ? sb[lane] : 0.f;
        #pragma unroll
        for (int o = 16; o > 0; o >>= 1) {
            a += __shfl_xor_sync(0xFFFFFFFFu, a, o);
            b += __shfl_xor_sync(0xFFFFFFFFu, b, o);
        }
        if (lane == 0) {
            atomicAdd(accA, (double)a);
            atomicAdd(accB, (double)b);
        }
    }
}

// ---------------------------------------------------------------------------
__device__ __forceinline__ void process_sample(const float* __restrict__ o2d,
                                               const float* __restrict__ m3d,
                                               int id, int x, int y, int z, int D,
                                               float& inter2, float& sumv) {
    const unsigned vox = ((unsigned)x * (unsigned)D + (unsigned)y) * (unsigned)D
                       + (unsigned)z;
    // issue both gathers early for MLP; predicate the accumulate on the win
    const float v = __ldg(o2d + id);
    const float m = __ldg(m3d + vox);
    const unsigned bit = 1u << (vox & 31u);
    const unsigned old = atomicOr(&g_bitmap[vox >> 5], bit);
    if (!(old & bit)) { inter2 += v * m; sumv += v; }
}

// ---------------------------------------------------------------------------
__global__ void __launch_bounds__(256)
fused_kernel(const float* __restrict__ o2d,
             const float* __restrict__ m2d,
             const float* __restrict__ m3d,
             const int*   __restrict__ index,
             const int*   __restrict__ midxyz,
             int N, int M, int V, int D) {
    const int tid    = blockIdx.x * blockDim.x + threadIdx.x;
    const int stride = gridDim.x * blockDim.x;

    // ---- scattered samples: dedup + gather-accumulate (4 samples / iter) ----
    float inter2 = 0.f, sumv = 0.f;
    {
        const int n4 = N >> 2;
        const int4* idx4 = reinterpret_cast<const int4*>(index);
        const int4* mid4 = reinterpret_cast<const int4*>(midxyz);
        for (int i = tid; i < n4; i += stride) {
            const int4 id = idx4[i];
            const int4 a  = mid4[3 * i + 0];
            const int4 b  = mid4[3 * i + 1];
            const int4 c  = mid4[3 * i + 2];
            process_sample(o2d, m3d, id.x, a.x, a.y, a.z, D, inter2, sumv);
            process_sample(o2d, m3d, id.y, a.w, b.x, b.y, D, inter2, sumv);
            process_sample(o2d, m3d, id.z, b.z, b.w, c.x, D, inter2, sumv);
            process_sample(o2d, m3d, id.w, c.y, c.z, c.w, D, inter2, sumv);
        }
        for (int i = (n4 << 2) + tid; i < N; i += stride) {
            process_sample(o2d, m3d, index[i],
                           midxyz[3 * i], midxyz[3 * i + 1], midxyz[3 * i + 2],
                           D, inter2, sumv);
        }
    }

    // ---- sequential sum of mask_3D ----
    float sm3 = 0.f;
    {
        const int v4 = V >> 2;
        const float4* m4 = reinterpret_cast<const float4*>(m3d);
        for (int i = tid; i < v4; i += stride) {
            const float4 m = m4[i];
            sm3 += (m.x + m.y) + (m.z + m.w);
        }
        for (int i = (v4 << 2) + tid; i < V; i += stride) sm3 += m3d[i];
    }

    // ---- 2D IoU partial sums ----
    float a2 = 0.f, b2 = 0.f;
    {
        const int m4n = M >> 2;
        const float4* o4 = reinterpret_cast<const float4*>(o2d);
        const float4* q4 = reinterpret_cast<const float4*>(m2d);
        for (int i = tid; i < m4n; i += stride) {
            const float4 o = o4[i];
            const float4 m = q4[i];
            a2 += o.x * m.x + o.y * m.y + o.z * m.z + o.w * m.w;
            b2 += (o.x + m.x) + (o.y + m.y) + (o.z + m.z) + (o.w + m.w);
        }
        for (int i = (m4n << 2) + tid; i < M; i += stride) {
            const float o = o2d[i], m = m2d[i];
            a2 += o * m;
            b2 += o + m;
        }
    }

    block_reduce_pair(a2, b2, &g_acc[0], &g_acc[1]);
    block_reduce_pair(inter2, sumv, &g_acc[2], &g_acc[3]);
    block_reduce_pair(sm3, 0.f, &g_acc[4], &g_acc[4]);  // second add is +0.0
}

// ---------------------------------------------------------------------------
__global__ void finalize_kernel(float* __restrict__ out) {
    const double eps = 1e-8;
    const double A1 = g_acc[0], B1 = g_acc[1];
    const double I2 = g_acc[2], SV = g_acc[3], SM = g_acc[4];
    const double union1 = B1 - A1;
    const double union2 = SV + SM - I2;
    const double l1 = 1.0 - (A1 + eps) / (union1 + eps);
    const double l2 = 1.0 - (I2 + eps) / (union2 + eps);
    out[0] = (float)l1;
    out[1] = (float)l2;
    out[2] = (float)(l1 + l2);
}

// ---------------------------------------------------------------------------
extern "C" void kernel_launch(void* const* d_in, const int* in_sizes, int n_in,
                              void* d_out, int out_size) {
    const float* o2d    = (const float*)d_in[0];
    const float* m2d    = (const float*)d_in[1];
    const float* m3d    = (const float*)d_in[2];
    const int*   index  = (const int*)  d_in[3];
    const int*   midxyz = (const int*)  d_in[4];

    const int M = in_sizes[0];        // H2*W2
    const int V = in_sizes[2];        // D^3
    const int N = in_sizes[3];        // samples

    int D = 1;
    while ((long long)(D + 1) * (D + 1) * (D + 1) <= (long long)V) ++D;
    if (D > DMAX) D = DMAX;

    float* out = (float*)d_out;

    const int TPB  = 256;
    const int GRID = 148 * 16;

    zero_kernel<<<148, TPB>>>();
    fused_kernel<<<GRID, TPB>>>(o2d, m2d, m3d, index, midxyz, N, M, V, D);
    finalize_kernel<<<1, 1>>>(out);
}